// round 16
// baseline (speedup 1.0000x reference)
#include <cuda_runtime.h>
#include <cuda_bf16.h>
#include <cuda_fp16.h>
#include <cstdint>
#include <math.h>

#define T_TOK 2176
#define HS    2048
#define NQKV  3072
#define NH    16
#define NKV   4
#define HD    128
#define MMETA 128
#define WWIN  512
#define SCALE_F 0.08838834764831845f
#define NEGV  -1.0e30f

// ---------------------------------------------------------------------------
// scratch buffers
// ---------------------------------------------------------------------------
__device__ int8_t g_A8h[T_TOK * HS];
__device__ int8_t g_A8l[T_TOK * HS];
__device__ int8_t g_W8h[NQKV * HS];                      // W transposed [n][k]
__device__ int8_t g_W8l[NQKV * HS];
__device__ float  g_sA[T_TOK];
__device__ unsigned g_sBbits[NQKV];                      // colmax |W| as float bits

__device__ int8_t g_Q8h[T_TOK * NH * HD];
__device__ int8_t g_Q8l[T_TOK * NH * HD];
__device__ float  g_sQ[T_TOK * NH];
__device__ int8_t g_K8h[T_TOK * NKV * HD];
__device__ int8_t g_K8l[T_TOK * NKV * HD];
__device__ float  g_sK[T_TOK * NKV];
__device__ __half g_Vh[T_TOK * NKV * HD];
__device__ float  g_invfreq[64];
__device__ float2 g_cs[T_TOK * 64];                      // (cos, sin) per (token, pair)

__device__ __forceinline__ uint32_t smem_to_u32(const void* p) {
    uint32_t a;
    asm("{ .reg .u64 t; cvta.to.shared.u64 t, %1; cvt.u32.u64 %0, t; }" : "=r"(a) : "l"(p));
    return a;
}
__device__ __forceinline__ uint32_t cvt_h2(float hi, float lo) {
    uint32_t d;
    asm("cvt.rn.f16x2.f32 %0, %1, %2;" : "=r"(d) : "f"(hi), "f"(lo));
    return d;
}
__device__ __forceinline__ void ldsm_x4(uint32_t* r, uint32_t addr) {
    asm volatile("ldmatrix.sync.aligned.m8n8.x4.shared.b16 {%0,%1,%2,%3}, [%4];"
                 : "=r"(r[0]), "=r"(r[1]), "=r"(r[2]), "=r"(r[3]) : "r"(addr));
}
__device__ __forceinline__ void ldsm_x4t(uint32_t* r, uint32_t addr) {
    asm volatile("ldmatrix.sync.aligned.m8n8.x4.trans.shared.b16 {%0,%1,%2,%3}, [%4];"
                 : "=r"(r[0]), "=r"(r[1]), "=r"(r[2]), "=r"(r[3]) : "r"(addr));
}
__device__ __forceinline__ void mma_s8(int* c, const uint32_t* a, const uint32_t* b) {
    asm volatile(
        "mma.sync.aligned.m16n8k32.row.col.s32.s8.s8.s32 "
        "{%0,%1,%2,%3}, {%4,%5,%6,%7}, {%8,%9}, {%0,%1,%2,%3};"
        : "+r"(c[0]), "+r"(c[1]), "+r"(c[2]), "+r"(c[3])
        : "r"(a[0]), "r"(a[1]), "r"(a[2]), "r"(a[3]), "r"(b[0]), "r"(b[1]));
}
__device__ __forceinline__ void mma_f16(float* c, const uint32_t* a, const uint32_t* b) {
    asm volatile(
        "mma.sync.aligned.m16n8k16.row.col.f32.f16.f16.f32 "
        "{%0,%1,%2,%3}, {%4,%5,%6,%7}, {%8,%9}, {%0,%1,%2,%3};"
        : "+f"(c[0]), "+f"(c[1]), "+f"(c[2]), "+f"(c[3])
        : "r"(a[0]), "r"(a[1]), "r"(a[2]), "r"(a[3]), "r"(b[0]), "r"(b[1]));
}
__device__ __forceinline__ void cp_async16(uint32_t dst, const void* src) {
    asm volatile("cp.async.ca.shared.global [%0], [%1], 16;" :: "r"(dst), "l"(src) : "memory");
}
__device__ __forceinline__ void cp_async4(uint32_t dst, const void* src) {
    asm volatile("cp.async.ca.shared.global [%0], [%1], 4;" :: "r"(dst), "l"(src) : "memory");
}
#define CP_COMMIT() asm volatile("cp.async.commit_group;" ::: "memory")
#define CP_WAIT1()  asm volatile("cp.async.wait_group 1;" ::: "memory")
#define CP_WAIT0()  asm volatile("cp.async.wait_group 0;" ::: "memory")

// ---------------------------------------------------------------------------
// inv_freq table (only place double-precision exp runs: 64 threads)
// ---------------------------------------------------------------------------
__global__ void init_invfreq_kernel() {
    int i = threadIdx.x;
    g_invfreq[i] = (float)exp(-(double)(2 * i) * (1.0 / 128.0) * log(10000.0));
}

// cos/sin table: reads fp32 inv_freq; same fp32 cosf/sinf numerics as R14.
__global__ void cs_table_kernel(const int* __restrict__ pos) {
    int idx = blockIdx.x * 256 + threadIdx.x;
    if (idx >= T_TOK * 64) return;
    int i = idx & 63;
    int t = idx >> 6;
    float ang = (float)pos[t] * g_invfreq[i];
    g_cs[idx] = make_float2(cosf(ang), sinf(ang));
}

// ---------------------------------------------------------------------------
// quantize A: one block per token row
// ---------------------------------------------------------------------------
__global__ void quant_a_kernel(const float* __restrict__ A) {
    const int t = blockIdx.x;
    const int tid = threadIdx.x;
    __shared__ float red[8];
    const float* row = A + (size_t)t * HS;
    float4 v0 = *(const float4*)&row[tid * 8];
    float4 v1 = *(const float4*)&row[tid * 8 + 4];
    float mx = fmaxf(fmaxf(fabsf(v0.x), fabsf(v0.y)), fmaxf(fabsf(v0.z), fabsf(v0.w)));
    mx = fmaxf(mx, fmaxf(fmaxf(fabsf(v1.x), fabsf(v1.y)), fmaxf(fabsf(v1.z), fabsf(v1.w))));
#pragma unroll
    for (int o = 16; o > 0; o >>= 1) mx = fmaxf(mx, __shfl_xor_sync(0xffffffffu, mx, o));
    if ((tid & 31) == 0) red[tid >> 5] = mx;
    __syncthreads();
    float m = fmaxf(fmaxf(fmaxf(red[0], red[1]), fmaxf(red[2], red[3])),
                    fmaxf(fmaxf(red[4], red[5]), fmaxf(red[6], red[7])));
    m = fmaxf(m, 1e-20f);
    if (tid == 0) g_sA[t] = m * (1.0f / 127.0f);
    float inv = 127.0f / m;

    float a[8] = { v0.x, v0.y, v0.z, v0.w, v1.x, v1.y, v1.z, v1.w };
    char hh[8], ll[8];
#pragma unroll
    for (int u = 0; u < 8; ++u) {
        float x = a[u] * inv;
        float h = rintf(x);
        int l = (int)rintf((x - h) * 256.0f);
        if (l > 127) l = 127;
        hh[u] = (char)(int)h;
        ll[u] = (char)l;
    }
    size_t o = (size_t)t * HS + tid * 8;
    *(uint2*)&g_A8h[o] = *(uint2*)hh;
    *(uint2*)&g_A8l[o] = *(uint2*)ll;
}

// ---------------------------------------------------------------------------
// W column max: float4 per thread (4 cols), idempotent atomicMax
// ---------------------------------------------------------------------------
__global__ void w_colmax_kernel(const float* __restrict__ W) {
    int c4 = blockIdx.x * 256 + threadIdx.x;       // float4 column group
    int r0 = blockIdx.y * 128;
    float4 mx = { 0.f, 0.f, 0.f, 0.f };
    for (int r = 0; r < 128; ++r) {
        float4 v = *(const float4*)&W[(size_t)(r0 + r) * NQKV + c4 * 4];
        mx.x = fmaxf(mx.x, fabsf(v.x));
        mx.y = fmaxf(mx.y, fabsf(v.y));
        mx.z = fmaxf(mx.z, fabsf(v.z));
        mx.w = fmaxf(mx.w, fabsf(v.w));
    }
    atomicMax(&g_sBbits[c4 * 4 + 0], __float_as_uint(mx.x));
    atomicMax(&g_sBbits[c4 * 4 + 1], __float_as_uint(mx.y));
    atomicMax(&g_sBbits[c4 * 4 + 2], __float_as_uint(mx.z));
    atomicMax(&g_sBbits[c4 * 4 + 3], __float_as_uint(mx.w));
}

// ---------------------------------------------------------------------------
// quantize + transpose W: 64x64 smem tile, uint4-packed STG.128 stores
// ---------------------------------------------------------------------------
__global__ void quant_w_kernel(const float* __restrict__ W) {
    __shared__ float tile[64][68];                 // pitch 68: 16B-aligned rows
    const int n0 = blockIdx.x * 64;
    const int k0 = blockIdx.y * 64;
    const int tid = threadIdx.x;

#pragma unroll
    for (int p = 0; p < 4; ++p) {
        int idx = p * 256 + tid;                   // 0..1023
        int row = idx >> 4;
        int cg  = idx & 15;
        *(float4*)&tile[row][cg * 4] =
            *(const float4*)&W[(size_t)(k0 + row) * NQKV + n0 + cg * 4];
    }
    __syncthreads();

    const int n  = tid & 63;
    const int kg = tid >> 6;
    float m = fmaxf(__uint_as_float(g_sBbits[n0 + n]), 1e-20f);
    float inv = 127.0f / m;
    char hh[16], ll[16];
#pragma unroll
    for (int j = 0; j < 16; ++j) {
        float x = tile[kg * 16 + j][n] * inv;
        float h = rintf(x);
        int l = (int)rintf((x - h) * 256.0f);
        if (l > 127) l = 127;
        hh[j] = (char)(int)h;
        ll[j] = (char)l;
    }
    size_t o = (size_t)(n0 + n) * HS + k0 + kg * 16;
    *(uint4*)&g_W8h[o] = *(uint4*)hh;
    *(uint4*)&g_W8l[o] = *(uint4*)ll;
}

// ---------------------------------------------------------------------------
// Stage 1: int8 2-digit GEMM.  CTA 64x128, 8 warps, 3-stage.
// Fused epilogue: bias + RoPE (table) + Q/K int8 quantization + V fp16.
// ---------------------------------------------------------------------------
#define A_T8 4096
#define B_T8 8192
#define STAGE8 24576
#define GEMM_SMEM (3 * STAGE8)

#define SWB(row, chunk) ((row) * 64 + ((((chunk) ^ (((row) >> 1) & 3))) << 4))

__global__ __launch_bounds__(256, 2)
void qkv_mma_kernel(const float* __restrict__ bias) {
    extern __shared__ char smem[];
    const uint32_t sb = smem_to_u32(smem);
    const int tid  = threadIdx.x;
    const int wid  = tid >> 5;
    const int lane = tid & 31;
    const int head = blockIdx.x;
    const int bm = blockIdx.y * 64;
    const int bn = head * 128;
    const int wm = (wid >> 2) * 32;
    const int wn = (wid & 3) * 32;

    const int8_t* srcA[2] = { g_A8h + (size_t)bm * HS, g_A8l + (size_t)bm * HS };
    const int8_t* srcB[2] = { g_W8h + (size_t)bn * HS, g_W8l + (size_t)bn * HS };

    auto issue_stage = [&](int c, int s) {
#pragma unroll
        for (int q = 0; q < 6; ++q) {
            int idx = q * 256 + tid;
            const int8_t* src;
            uint32_t dst;
            if (idx < 512) {
                int arr = idx >> 8;
                int rem = idx & 255;
                int row = rem >> 2, seg = rem & 3;
                src = srcA[arr] + (size_t)row * HS + c * 64 + seg * 16;
                dst = sb + s * STAGE8 + arr * A_T8 + SWB(row, seg);
            } else {
                int arr = (idx - 512) >> 9;
                int rem = idx & 511;
                int row = rem >> 2, seg = rem & 3;
                src = srcB[arr] + (size_t)row * HS + c * 64 + seg * 16;
                dst = sb + s * STAGE8 + 2 * A_T8 + arr * B_T8 + SWB(row, seg);
            }
            cp_async16(dst, src);
        }
    };

    int D1[2][4][4], D2[2][4][4];
#pragma unroll
    for (int i = 0; i < 2; ++i)
#pragma unroll
        for (int j = 0; j < 4; ++j)
#pragma unroll
            for (int q = 0; q < 4; ++q) { D1[i][j][q] = 0; D2[i][j][q] = 0; }

    issue_stage(0, 0); CP_COMMIT();
    issue_stage(1, 1); CP_COMMIT();

    const int arow  = wm + (lane & 15);
    const int ac0   = lane >> 4;
    const int brow4 = (lane & 7) + ((lane >> 4) & 1) * 8;
    const int bc0   = (lane >> 3) & 1;

    const int NCH = HS / 64;
    int buf = 0;
    for (int c = 0; c < NCH; ++c) {
        CP_WAIT1();
        __syncthreads();

        if (c + 2 < NCH) {
            int nb = buf - 1;
            if (nb < 0) nb = 2;
            issue_stage(c + 2, nb);
        }
        CP_COMMIT();

        const uint32_t base = sb + buf * STAGE8;
#pragma unroll
        for (int ks = 0; ks < 2; ++ks) {
            uint32_t ah[2][4], al[2][4];
#pragma unroll
            for (int i = 0; i < 2; ++i) {
                int row = arow + i * 16;
                uint32_t ad = base + SWB(row, ac0 + ks * 2);
                ldsm_x4(ah[i], ad);
                ldsm_x4(al[i], ad + A_T8);
            }
#pragma unroll
            for (int jp = 0; jp < 2; ++jp) {
                uint32_t bh[4], bl[4];
                int row = wn + jp * 16 + brow4;
                uint32_t bd = base + 2 * A_T8 + SWB(row, bc0 + ks * 2);
                ldsm_x4(bh, bd);
                ldsm_x4(bl, bd + B_T8);
#pragma unroll
                for (int i = 0; i < 2; ++i) {
                    mma_s8(D1[i][2 * jp], ah[i], bh);
                    mma_s8(D2[i][2 * jp], ah[i], bl);
                    mma_s8(D2[i][2 * jp], al[i], bh);
                    mma_s8(D1[i][2 * jp + 1], ah[i], bh + 2);
                    mma_s8(D2[i][2 * jp + 1], ah[i], bl + 2);
                    mma_s8(D2[i][2 * jp + 1], al[i], bh + 2);
                }
            }
        }
        buf = (buf == 2) ? 0 : buf + 1;
    }

    // ---- dequant + bias into smem staging ----
    CP_WAIT0();
    __syncthreads();
    float* Ct = (float*)smem;                 // [64][132]
    const int r  = lane >> 2;
    const int cc = (lane & 3) * 2;
#pragma unroll
    for (int i = 0; i < 2; ++i) {
        int row0 = wm + i * 16 + r;
        float sa0 = g_sA[bm + row0];
        float sa1 = g_sA[bm + row0 + 8];
#pragma unroll
        for (int j = 0; j < 4; ++j) {
            int col = wn + j * 8 + cc;
            float sb0 = __uint_as_float(g_sBbits[bn + col])     * (1.0f / 127.0f);
            float sb1 = __uint_as_float(g_sBbits[bn + col + 1]) * (1.0f / 127.0f);
            float b0 = bias[bn + col], b1 = bias[bn + col + 1];
            Ct[row0 * 132 + col]           = ((float)D1[i][j][0] + (float)D2[i][j][0] * (1.0f / 256.0f)) * sa0 * sb0 + b0;
            Ct[row0 * 132 + col + 1]       = ((float)D1[i][j][1] + (float)D2[i][j][1] * (1.0f / 256.0f)) * sa0 * sb1 + b1;
            Ct[(row0 + 8) * 132 + col]     = ((float)D1[i][j][2] + (float)D2[i][j][2] * (1.0f / 256.0f)) * sa1 * sb0 + b0;
            Ct[(row0 + 8) * 132 + col + 1] = ((float)D1[i][j][3] + (float)D2[i][j][3] * (1.0f / 256.0f)) * sa1 * sb1 + b1;
        }
    }
    __syncthreads();

    if (head < 20) {
        // ---- RoPE in place via table ----
#pragma unroll 4
        for (int p = 0; p < 16; ++p) {
            int idx = p * 256 + tid;
            int row = idx >> 6;
            int i   = idx & 63;
            int t   = bm + row;
            float x1 = Ct[row * 132 + i];
            float x2 = Ct[row * 132 + i + 64];
            float2 cs = g_cs[t * 64 + i];
            float y1 = x1 * cs.x - x2 * cs.y;
            float y2 = x2 * cs.x + x1 * cs.y;
            if (head < 16) { y1 *= SCALE_F; y2 *= SCALE_F; }
            Ct[row * 132 + i]      = y1;
            Ct[row * 132 + i + 64] = y2;
        }
        __syncthreads();

        // ---- fused per-row quantization ----
        {
            int row = tid >> 2;
            int l4  = tid & 3;
            int t   = bm + row;
            const float* rp = &Ct[row * 132 + l4 * 32];
            float v[32];
#pragma unroll
            for (int u = 0; u < 8; ++u)
                *(float4*)&v[u * 4] = *(const float4*)&rp[u * 4];
            float mx = 0.f;
#pragma unroll
            for (int u = 0; u < 32; ++u) mx = fmaxf(mx, fabsf(v[u]));
            mx = fmaxf(mx, __shfl_xor_sync(0xffffffffu, mx, 1));
            mx = fmaxf(mx, __shfl_xor_sync(0xffffffffu, mx, 2));
            float m = fmaxf(mx, 1e-20f);
            if (l4 == 0) {
                if (head < 16) g_sQ[(size_t)t * NH + head]         = m * (1.0f / 127.0f);
                else           g_sK[(size_t)t * NKV + (head - 16)] = m * (1.0f / 127.0f);
            }
            float inv = 127.0f / m;
            char hh[32], ll[32];
#pragma unroll
            for (int u = 0; u < 32; ++u) {
                float x = v[u] * inv;
                float hq = rintf(x);
                int l = (int)rintf((x - hq) * 256.0f);
                if (l > 127) l = 127;
                hh[u] = (char)(int)hq;
                ll[u] = (char)l;
            }
            int8_t* dh;
            int8_t* dl;
            if (head < 16) {
                size_t o = (size_t)t * (NH * HD) + head * HD + l4 * 32;
                dh = &g_Q8h[o]; dl = &g_Q8l[o];
            } else {
                size_t o = (size_t)t * (NKV * HD) + (head - 16) * HD + l4 * 32;
                dh = &g_K8h[o]; dl = &g_K8l[o];
            }
            *(uint4*)&dh[0]  = *(uint4*)&hh[0];
            *(uint4*)&dh[16] = *(uint4*)&hh[16];
            *(uint4*)&dl[0]  = *(uint4*)&ll[0];
            *(uint4*)&dl[16] = *(uint4*)&ll[16];
        }
    } else {
        // ---- V: single fp16 ----
#pragma unroll 4
        for (int p = 0; p < 16; ++p) {
            int idx = p * 256 + tid;
            int row = idx >> 6;
            int i   = idx & 63;
            int t   = bm + row;
            float x1 = Ct[row * 132 + i];
            float x2 = Ct[row * 132 + i + 64];
            size_t o = (size_t)t * (NKV * HD) + (head - 20) * HD + i;
            g_Vh[o]      = __float2half_rn(x1);
            g_Vh[o + 64] = __float2half_rn(x2);
        }
    }
}

// ---------------------------------------------------------------------------
// Stage 3: attention.  QK^T int8 2-digit, PV fp16 (single-digit V).
// 2 heads/CTA, 2-stage cp.async KV, Q staged once, occ 1.  (R14 version)
// ---------------------------------------------------------------------------
#define K8_B 8192
#define V_B  17408
#define ASTG (2 * K8_B + V_B + 256)       // 34048
#define Q_TOTAL 32768
#define ATTN_SMEM (Q_TOTAL + 2 * ASTG)    // 100864

#define SWQ(row, chunk) ((row) * 128 + ((((chunk) ^ ((row) & 7))) << 4))

__global__ __launch_bounds__(256, 1)
void attn_mma_kernel(float* __restrict__ out) {
    extern __shared__ char smc[];
    const uint32_t smu = smem_to_u32(smc);
    const int tid  = threadIdx.x;
    const int wid  = tid >> 5;
    const int lane = tid & 31;

    const int qt   = 33 - blockIdx.x;
    const int hp   = blockIdx.y;
    const int head = hp * 2 + (wid >> 2);
    const int kvh  = hp >> 1;
    const int t0   = qt * 64;
    const int mrow = (wid & 3) * 16;

    const int r  = lane >> 2;
    const int cc = (lane & 3) * 2;

    int kts[12];
    int nkt = 0;
    if (t0 >= MMETA && qt >= 10) {
        kts[nkt++] = 0; kts[nkt++] = 1;
        for (int k = qt - 8; k <= qt; ++k) kts[nkt++] = k;
    } else {
        for (int k = 0; k <= qt; ++k) kts[nkt++] = k;
    }

    // ---- stage Q8 tiles (2 heads x 2 digits) ----
#pragma unroll
    for (int q = 0; q < 8; ++q) {
        int idx = q * 256 + tid;
        int hd  = idx >> 10;
        int rem = idx & 1023;
        int dg  = rem >> 9;
        int r2  = rem & 511;
        int row = r2 >> 3;
        int seg = r2 & 7;
        const int8_t* src = (dg ? g_Q8l : g_Q8h) +
                            (size_t)(t0 + row) * (NH * HD) + (hp * 2 + hd) * HD + seg * 16;
        cp_async16(smu + hd * 16384 + dg * 8192 + SWQ(row, seg), src);
    }

    auto issue = [&](int ti, int buf) {
        int s0 = kts[ti] * 64;
        uint32_t base = smu + Q_TOTAL + buf * ASTG;
#pragma unroll
        for (int q = 0; q < 8; ++q) {
            int idx = q * 256 + tid;
            if (idx < 1024) {
                int dg = idx >> 9, rem = idx & 511, row = rem >> 3, seg = rem & 7;
                const int8_t* src = (dg ? g_K8l : g_K8h) +
                                    (size_t)(s0 + row) * (NKV * HD) + kvh * HD + seg * 16;
                cp_async16(base + dg * K8_B + SWQ(row, seg), src);
            } else {
                int v = idx - 1024, row = v >> 4, ch = v & 15;
                const __half* src = g_Vh +
                                    (size_t)(s0 + row) * (NKV * HD) + kvh * HD + ch * 8;
                cp_async16(base + 2 * K8_B + row * 272 + ch * 16, src);
            }
        }
        if (tid < 64)
            cp_async4(base + 2 * K8_B + V_B + tid * 4, &g_sK[(size_t)(s0 + tid) * NKV + kvh]);
    };

    const int tr0 = t0 + mrow + r;
    const int tr1 = tr0 + 8;
    const float sq0 = g_sQ[(size_t)tr0 * NH + head];
    const float sq1 = g_sQ[(size_t)tr1 * NH + head];

    const int brow4 = (lane & 7) + ((lane >> 4) & 1) * 8;
    const int bc0   = (lane >> 3) & 1;
    const uint32_t voff = ((lane & 7) + ((lane >> 3) & 1) * 8) * 272 + ((lane >> 3) >> 1) * 16;

    float oacc[16][4];
#pragma unroll
    for (int j = 0; j < 16; ++j)
#pragma unroll
        for (int q = 0; q < 4; ++q) oacc[j][q] = 0.f;
    float m0 = -3.0e38f, m1 = -3.0e38f, l0 = 0.f, l1 = 0.f;

    uint32_t qh[4][4], ql[4][4];

    issue(0, 0); CP_COMMIT();

    for (int it = 0; it < nkt; ++it) {
        if (it + 1 < nkt) issue(it + 1, (it + 1) & 1);
        CP_COMMIT();
        CP_WAIT1();
        __syncthreads();

        const uint32_t base = smu + Q_TOTAL + (it & 1) * ASTG;
        const float* sKs = (const float*)(smc + Q_TOTAL + (it & 1) * ASTG + 2 * K8_B + V_B);
        const int s0 = kts[it] * 64;

        if (it == 0) {
            uint32_t qb = smu + (wid >> 2) * 16384;
#pragma unroll
            for (int kc = 0; kc < 4; ++kc) {
                uint32_t ad = qb + SWQ(mrow + (lane & 15), kc * 2 + (lane >> 4));
                ldsm_x4(qh[kc], ad);
                ldsm_x4(ql[kc], ad + 8192);
            }
        }

        // ---- S = Q K^T (int8 2-digit) ----
        int S1[8][4], S2[8][4];
#pragma unroll
        for (int j = 0; j < 8; ++j)
#pragma unroll
            for (int q = 0; q < 4; ++q) { S1[j][q] = 0; S2[j][q] = 0; }

#pragma unroll
        for (int j = 0; j < 4; ++j) {
#pragma unroll
            for (int kc = 0; kc < 4; ++kc) {
                uint32_t kh[4], kl[4];
                uint32_t bd = base + SWQ(j * 16 + brow4, kc * 2 + bc0);
                ldsm_x4(kh, bd);
                ldsm_x4(kl, bd + K8_B);
                mma_s8(S1[2 * j], qh[kc], kh);
                mma_s8(S2[2 * j], qh[kc], kl);
                mma_s8(S2[2 * j], ql[kc], kh);
                mma_s8(S1[2 * j + 1], qh[kc], kh + 2);
                mma_s8(S2[2 * j + 1], qh[kc], kl + 2);
                mma_s8(S2[2 * j + 1], ql[kc], kh + 2);
            }
        }

        // ---- dequant + mask ----
        float sacc[8][4];
#pragma unroll
        for (int j = 0; j < 8; ++j) {
            int c0 = j * 8 + cc;
            float k0s = sKs[c0], k1s = sKs[c0 + 1];
            sacc[j][0] = ((float)S1[j][0] + (float)S2[j][0] * (1.0f / 256.0f)) * (sq0 * k0s);
            sacc[j][1] = ((float)S1[j][1] + (float)S2[j][1] * (1.0f / 256.0f)) * (sq0 * k1s);
            sacc[j][2] = ((float)S1[j][2] + (float)S2[j][2] * (1.0f / 256.0f)) * (sq1 * k0s);
            sacc[j][3] = ((float)S1[j][3] + (float)S2[j][3] * (1.0f / 256.0f)) * (sq1 * k1s);
        }

#pragma unroll
        for (int j = 0; j < 8; ++j) {
            int sb0 = s0 + j * 8 + cc;
#pragma unroll
            for (int cx = 0; cx < 2; ++cx) {
                int s = sb0 + cx;
                bool v0 = (tr0 < MMETA) ? (s <= tr0)
                                        : ((s < MMETA) || ((s <= tr0) && (tr0 - s < WWIN)));
                bool v1 = (tr1 < MMETA) ? (s <= tr1)
                                        : ((s < MMETA) || ((s <= tr1) && (tr1 - s < WWIN)));
                if (!v0) sacc[j][cx]     = NEGV;
                if (!v1) sacc[j][cx + 2] = NEGV;
            }
        }

        // ---- online softmax (fp16 P, sums from rounded values) ----
        float mx0 = NEGV, mx1 = NEGV;
#pragma unroll
        for (int j = 0; j < 8; ++j) {
            mx0 = fmaxf(mx0, fmaxf(sacc[j][0], sacc[j][1]));
            mx1 = fmaxf(mx1, fmaxf(sacc[j][2], sacc[j][3]));
        }
        mx0 = fmaxf(mx0, __shfl_xor_sync(0xffffffffu, mx0, 1));
        mx0 = fmaxf(mx0, __shfl_xor_sync(0xffffffffu, mx0, 2));
        mx1 = fmaxf(mx1, __shfl_xor_sync(0xffffffffu, mx1, 1));
        mx1 = fmaxf(mx1, __shfl_xor_sync(0xffffffffu, mx1, 2));

        float mn0 = fmaxf(m0, mx0);
        float mn1 = fmaxf(m1, mx1);
        float al0 = __expf(m0 - mn0);
        float al1 = __expf(m1 - mn1);
        m0 = mn0; m1 = mn1;

        uint32_t pp[8][2];
        float sum0 = 0.f, sum1 = 0.f;
#pragma unroll
        for (int j = 0; j < 8; ++j) {
            float p0 = __expf(sacc[j][0] - m0);
            float p1 = __expf(sacc[j][1] - m0);
            float p2 = __expf(sacc[j][2] - m1);
            float p3 = __expf(sacc[j][3] - m1);
            uint32_t h0 = cvt_h2(p1, p0);
            uint32_t h1 = cvt_h2(p3, p2);
            pp[j][0] = h0;
            pp[j][1] = h1;
            float2 f0 = __half22float2(*reinterpret_cast<__half2*>(&h0));
            float2 f1 = __half22float2(*reinterpret_cast<__half2*>(&h1));
            sum0 += f0.x + f0.y;
            sum1 += f1.x + f1.y;
        }
        sum0 += __shfl_xor_sync(0xffffffffu, sum0, 1);
        sum0 += __shfl_xor_sync(0xffffffffu, sum0, 2);
        sum1 += __shfl_xor_sync(0xffffffffu, sum1, 1);
        sum1 += __shfl_xor_sync(0xffffffffu, sum1, 2);
        l0 = l0 * al0 + sum0;
        l1 = l1 * al1 + sum1;

#pragma unroll
        for (int j = 0; j < 16; ++j) {
            oacc[j][0] *= al0; oacc[j][1] *= al0;
            oacc[j][2] *= al1; oacc[j][3] *= al1;
        }

        // ---- O += P V (fp16, single-digit V) ----
        const uint32_t vbase = base + 2 * K8_B;
#pragma unroll
        for (int kt = 0; kt < 4; ++kt) {
            uint32_t phi[4] = { pp[2 * kt][0], pp[2 * kt][1], pp[2 * kt + 1][0], pp[2 * kt + 1][1] };
            uint32_t ktb = vbase + kt * (16 * 272) + voff;
#pragma unroll
            for (int j2 = 0; j2 < 8; ++j2) {
                uint32_t vh[4];
                ldsm_x4t(vh, ktb + j2 * 32);
                mma_f16(oacc[2 * j2], phi, vh);
                mma_f16(oacc[2 * j2 + 1], phi, vh + 2);
            }
        }
        __syncthreads();
    }

    float inv0 = 1.0f / l0;
    float inv1 = 1.0f / l1;
    float* ob0 = &out[(size_t)tr0 * (NH * HD) + head * HD + cc];
    float* ob1 = &out[(size_t)tr1 * (NH * HD) + head * HD + cc];
#pragma unroll
    for (int j = 0; j < 16; ++j) {
        float2 v0 = { oacc[j][0] * inv0, oacc[j][1] * inv0 };
        float2 v1 = { oacc[j][2] * inv1, oacc[j][3] * inv1 };
        *(float2*)&ob0[j * 8] = v0;
        *(float2*)&ob1[j * 8] = v1;
    }
}

// ---------------------------------------------------------------------------
extern "C" void kernel_launch(void* const* d_in, const int* in_sizes, int n_in,
                              void* d_out, int out_size) {
    const float* hs   = (const float*)d_in[0];
    const float* w    = (const float*)d_in[1];
    const float* bias = (const float*)d_in[2];
    const int*   pos  = (const int*)d_in[3];
    float* out = (float*)d_out;

    init_invfreq_kernel<<<1, 64>>>();
    cs_table_kernel<<<(T_TOK * 64 + 255) / 256, 256>>>(pos);
    quant_a_kernel<<<T_TOK, 256>>>(hs);
    w_colmax_kernel<<<dim3(NQKV / 4 / 256, HS / 128), 256>>>(w);
    quant_w_kernel<<<dim3(NQKV / 64, HS / 64), 256>>>(w);

    cudaFuncSetAttribute(qkv_mma_kernel, cudaFuncAttributeMaxDynamicSharedMemorySize, GEMM_SMEM);
    qkv_mma_kernel<<<dim3(24, T_TOK / 64), 256, GEMM_SMEM>>>(bias);

    cudaFuncSetAttribute(attn_mma_kernel, cudaFuncAttributeMaxDynamicSharedMemorySize, ATTN_SMEM);
    attn_mma_kernel<<<dim3(34, 8), 256, ATTN_SMEM>>>(out);
}

// round 17
// speedup vs baseline: 1.0500x; 1.0500x over previous
#include <cuda_runtime.h>
#include <cuda_bf16.h>
#include <cuda_fp16.h>
#include <cstdint>
#include <math.h>

#define T_TOK 2176
#define HS    2048
#define NQKV  3072
#define NH    16
#define NKV   4
#define HD    128
#define MMETA 128
#define WWIN  512
#define SCALE_F 0.08838834764831845f
#define NEGV  -1.0e30f

// ---------------------------------------------------------------------------
// scratch buffers
// ---------------------------------------------------------------------------
__device__ int8_t g_A8h[T_TOK * HS];
__device__ int8_t g_A8l[T_TOK * HS];
__device__ int8_t g_W8h[NQKV * HS];                      // W transposed [n][k]
__device__ int8_t g_W8l[NQKV * HS];
__device__ float  g_sA[T_TOK];
__device__ unsigned g_sBbits[NQKV];                      // colmax |W| as float bits

__device__ int8_t g_Q8h[T_TOK * NH * HD];
__device__ int8_t g_Q8l[T_TOK * NH * HD];
__device__ float  g_sQ[T_TOK * NH];
__device__ int8_t g_K8h[T_TOK * NKV * HD];
__device__ int8_t g_K8l[T_TOK * NKV * HD];
__device__ float  g_sK[T_TOK * NKV];
__device__ __half g_Vh[T_TOK * NKV * HD];
__device__ float  g_invfreq[64];
__device__ float2 g_cs[T_TOK * 64];                      // (cos, sin) per (token, pair)

__device__ __forceinline__ uint32_t smem_to_u32(const void* p) {
    uint32_t a;
    asm("{ .reg .u64 t; cvta.to.shared.u64 t, %1; cvt.u32.u64 %0, t; }" : "=r"(a) : "l"(p));
    return a;
}
__device__ __forceinline__ uint32_t cvt_h2(float hi, float lo) {
    uint32_t d;
    asm("cvt.rn.f16x2.f32 %0, %1, %2;" : "=r"(d) : "f"(hi), "f"(lo));
    return d;
}
__device__ __forceinline__ void ldsm_x4(uint32_t* r, uint32_t addr) {
    asm volatile("ldmatrix.sync.aligned.m8n8.x4.shared.b16 {%0,%1,%2,%3}, [%4];"
                 : "=r"(r[0]), "=r"(r[1]), "=r"(r[2]), "=r"(r[3]) : "r"(addr));
}
__device__ __forceinline__ void ldsm_x4t(uint32_t* r, uint32_t addr) {
    asm volatile("ldmatrix.sync.aligned.m8n8.x4.trans.shared.b16 {%0,%1,%2,%3}, [%4];"
                 : "=r"(r[0]), "=r"(r[1]), "=r"(r[2]), "=r"(r[3]) : "r"(addr));
}
__device__ __forceinline__ void mma_s8(int* c, const uint32_t* a, const uint32_t* b) {
    asm volatile(
        "mma.sync.aligned.m16n8k32.row.col.s32.s8.s8.s32 "
        "{%0,%1,%2,%3}, {%4,%5,%6,%7}, {%8,%9}, {%0,%1,%2,%3};"
        : "+r"(c[0]), "+r"(c[1]), "+r"(c[2]), "+r"(c[3])
        : "r"(a[0]), "r"(a[1]), "r"(a[2]), "r"(a[3]), "r"(b[0]), "r"(b[1]));
}
__device__ __forceinline__ void mma_f16(float* c, const uint32_t* a, const uint32_t* b) {
    asm volatile(
        "mma.sync.aligned.m16n8k16.row.col.f32.f16.f16.f32 "
        "{%0,%1,%2,%3}, {%4,%5,%6,%7}, {%8,%9}, {%0,%1,%2,%3};"
        : "+f"(c[0]), "+f"(c[1]), "+f"(c[2]), "+f"(c[3])
        : "r"(a[0]), "r"(a[1]), "r"(a[2]), "r"(a[3]), "r"(b[0]), "r"(b[1]));
}
__device__ __forceinline__ void cp_async16(uint32_t dst, const void* src) {
    asm volatile("cp.async.ca.shared.global [%0], [%1], 16;" :: "r"(dst), "l"(src) : "memory");
}
__device__ __forceinline__ void cp_async4(uint32_t dst, const void* src) {
    asm volatile("cp.async.ca.shared.global [%0], [%1], 4;" :: "r"(dst), "l"(src) : "memory");
}
#define CP_COMMIT() asm volatile("cp.async.commit_group;" ::: "memory")
#define CP_WAIT1()  asm volatile("cp.async.wait_group 1;" ::: "memory")
#define CP_WAIT0()  asm volatile("cp.async.wait_group 0;" ::: "memory")

// ---------------------------------------------------------------------------
// inv_freq table (only place double-precision exp runs: 64 threads)
// ---------------------------------------------------------------------------
__global__ void init_invfreq_kernel() {
    int i = threadIdx.x;
    g_invfreq[i] = (float)exp(-(double)(2 * i) * (1.0 / 128.0) * log(10000.0));
}

// cos/sin table: reads fp32 inv_freq; same fp32 cosf/sinf numerics as R14.
__global__ void cs_table_kernel(const int* __restrict__ pos) {
    int idx = blockIdx.x * 256 + threadIdx.x;
    if (idx >= T_TOK * 64) return;
    int i = idx & 63;
    int t = idx >> 6;
    float ang = (float)pos[t] * g_invfreq[i];
    g_cs[idx] = make_float2(cosf(ang), sinf(ang));
}

// ---------------------------------------------------------------------------
// quantize A: one block per token row
// ---------------------------------------------------------------------------
__global__ void quant_a_kernel(const float* __restrict__ A) {
    const int t = blockIdx.x;
    const int tid = threadIdx.x;
    __shared__ float red[8];
    const float* row = A + (size_t)t * HS;
    float4 v0 = *(const float4*)&row[tid * 8];
    float4 v1 = *(const float4*)&row[tid * 8 + 4];
    float mx = fmaxf(fmaxf(fabsf(v0.x), fabsf(v0.y)), fmaxf(fabsf(v0.z), fabsf(v0.w)));
    mx = fmaxf(mx, fmaxf(fmaxf(fabsf(v1.x), fabsf(v1.y)), fmaxf(fabsf(v1.z), fabsf(v1.w))));
#pragma unroll
    for (int o = 16; o > 0; o >>= 1) mx = fmaxf(mx, __shfl_xor_sync(0xffffffffu, mx, o));
    if ((tid & 31) == 0) red[tid >> 5] = mx;
    __syncthreads();
    float m = fmaxf(fmaxf(fmaxf(red[0], red[1]), fmaxf(red[2], red[3])),
                    fmaxf(fmaxf(red[4], red[5]), fmaxf(red[6], red[7])));
    m = fmaxf(m, 1e-20f);
    if (tid == 0) g_sA[t] = m * (1.0f / 127.0f);
    float inv = 127.0f / m;

    float a[8] = { v0.x, v0.y, v0.z, v0.w, v1.x, v1.y, v1.z, v1.w };
    char hh[8], ll[8];
#pragma unroll
    for (int u = 0; u < 8; ++u) {
        float x = a[u] * inv;
        float h = rintf(x);
        int l = (int)rintf((x - h) * 256.0f);
        if (l > 127) l = 127;
        hh[u] = (char)(int)h;
        ll[u] = (char)l;
    }
    size_t o = (size_t)t * HS + tid * 8;
    *(uint2*)&g_A8h[o] = *(uint2*)hh;
    *(uint2*)&g_A8l[o] = *(uint2*)ll;
}

// ---------------------------------------------------------------------------
// W column max: float4 per thread (4 cols), 32-row chunks -> 192 CTAs
// ---------------------------------------------------------------------------
__global__ void w_colmax_kernel(const float* __restrict__ W) {
    int c4 = blockIdx.x * 256 + threadIdx.x;       // float4 column group
    int r0 = blockIdx.y * 32;
    float4 mx = { 0.f, 0.f, 0.f, 0.f };
#pragma unroll 4
    for (int r = 0; r < 32; ++r) {
        float4 v = *(const float4*)&W[(size_t)(r0 + r) * NQKV + c4 * 4];
        mx.x = fmaxf(mx.x, fabsf(v.x));
        mx.y = fmaxf(mx.y, fabsf(v.y));
        mx.z = fmaxf(mx.z, fabsf(v.z));
        mx.w = fmaxf(mx.w, fabsf(v.w));
    }
    atomicMax(&g_sBbits[c4 * 4 + 0], __float_as_uint(mx.x));
    atomicMax(&g_sBbits[c4 * 4 + 1], __float_as_uint(mx.y));
    atomicMax(&g_sBbits[c4 * 4 + 2], __float_as_uint(mx.z));
    atomicMax(&g_sBbits[c4 * 4 + 3], __float_as_uint(mx.w));
}

// ---------------------------------------------------------------------------
// quantize + transpose W: 64x64 smem tile, uint4-packed STG.128 stores
// ---------------------------------------------------------------------------
__global__ void quant_w_kernel(const float* __restrict__ W) {
    __shared__ float tile[64][68];                 // pitch 68: 16B-aligned rows
    const int n0 = blockIdx.x * 64;
    const int k0 = blockIdx.y * 64;
    const int tid = threadIdx.x;

#pragma unroll
    for (int p = 0; p < 4; ++p) {
        int idx = p * 256 + tid;                   // 0..1023
        int row = idx >> 4;
        int cg  = idx & 15;
        *(float4*)&tile[row][cg * 4] =
            *(const float4*)&W[(size_t)(k0 + row) * NQKV + n0 + cg * 4];
    }
    __syncthreads();

    const int n  = tid & 63;
    const int kg = tid >> 6;
    float m = fmaxf(__uint_as_float(g_sBbits[n0 + n]), 1e-20f);
    float inv = 127.0f / m;
    char hh[16], ll[16];
#pragma unroll
    for (int j = 0; j < 16; ++j) {
        float x = tile[kg * 16 + j][n] * inv;
        float h = rintf(x);
        int l = (int)rintf((x - h) * 256.0f);
        if (l > 127) l = 127;
        hh[j] = (char)(int)h;
        ll[j] = (char)l;
    }
    size_t o = (size_t)(n0 + n) * HS + k0 + kg * 16;
    *(uint4*)&g_W8h[o] = *(uint4*)hh;
    *(uint4*)&g_W8l[o] = *(uint4*)ll;
}

// ---------------------------------------------------------------------------
// Stage 1: int8 2-digit GEMM.  CTA 64x128, 8 warps, 3-stage.
// Fused epilogue: bias + RoPE (table) + Q/K int8 quantization + V fp16.
// ---------------------------------------------------------------------------
#define A_T8 4096
#define B_T8 8192
#define STAGE8 24576
#define GEMM_SMEM (3 * STAGE8)

#define SWB(row, chunk) ((row) * 64 + ((((chunk) ^ (((row) >> 1) & 3))) << 4))

__global__ __launch_bounds__(256, 2)
void qkv_mma_kernel(const float* __restrict__ bias) {
    extern __shared__ char smem[];
    const uint32_t sb = smem_to_u32(smem);
    const int tid  = threadIdx.x;
    const int wid  = tid >> 5;
    const int lane = tid & 31;
    const int head = blockIdx.x;
    const int bm = blockIdx.y * 64;
    const int bn = head * 128;
    const int wm = (wid >> 2) * 32;
    const int wn = (wid & 3) * 32;

    const int8_t* srcA[2] = { g_A8h + (size_t)bm * HS, g_A8l + (size_t)bm * HS };
    const int8_t* srcB[2] = { g_W8h + (size_t)bn * HS, g_W8l + (size_t)bn * HS };

    auto issue_stage = [&](int c, int s) {
#pragma unroll
        for (int q = 0; q < 6; ++q) {
            int idx = q * 256 + tid;
            const int8_t* src;
            uint32_t dst;
            if (idx < 512) {
                int arr = idx >> 8;
                int rem = idx & 255;
                int row = rem >> 2, seg = rem & 3;
                src = srcA[arr] + (size_t)row * HS + c * 64 + seg * 16;
                dst = sb + s * STAGE8 + arr * A_T8 + SWB(row, seg);
            } else {
                int arr = (idx - 512) >> 9;
                int rem = idx & 511;
                int row = rem >> 2, seg = rem & 3;
                src = srcB[arr] + (size_t)row * HS + c * 64 + seg * 16;
                dst = sb + s * STAGE8 + 2 * A_T8 + arr * B_T8 + SWB(row, seg);
            }
            cp_async16(dst, src);
        }
    };

    int D1[2][4][4], D2[2][4][4];
#pragma unroll
    for (int i = 0; i < 2; ++i)
#pragma unroll
        for (int j = 0; j < 4; ++j)
#pragma unroll
            for (int q = 0; q < 4; ++q) { D1[i][j][q] = 0; D2[i][j][q] = 0; }

    issue_stage(0, 0); CP_COMMIT();
    issue_stage(1, 1); CP_COMMIT();

    const int arow  = wm + (lane & 15);
    const int ac0   = lane >> 4;
    const int brow4 = (lane & 7) + ((lane >> 4) & 1) * 8;
    const int bc0   = (lane >> 3) & 1;

    const int NCH = HS / 64;
    int buf = 0;
    for (int c = 0; c < NCH; ++c) {
        CP_WAIT1();
        __syncthreads();

        if (c + 2 < NCH) {
            int nb = buf - 1;
            if (nb < 0) nb = 2;
            issue_stage(c + 2, nb);
        }
        CP_COMMIT();

        const uint32_t base = sb + buf * STAGE8;
#pragma unroll
        for (int ks = 0; ks < 2; ++ks) {
            uint32_t ah[2][4], al[2][4];
#pragma unroll
            for (int i = 0; i < 2; ++i) {
                int row = arow + i * 16;
                uint32_t ad = base + SWB(row, ac0 + ks * 2);
                ldsm_x4(ah[i], ad);
                ldsm_x4(al[i], ad + A_T8);
            }
#pragma unroll
            for (int jp = 0; jp < 2; ++jp) {
                uint32_t bh[4], bl[4];
                int row = wn + jp * 16 + brow4;
                uint32_t bd = base + 2 * A_T8 + SWB(row, bc0 + ks * 2);
                ldsm_x4(bh, bd);
                ldsm_x4(bl, bd + B_T8);
#pragma unroll
                for (int i = 0; i < 2; ++i) {
                    mma_s8(D1[i][2 * jp], ah[i], bh);
                    mma_s8(D2[i][2 * jp], ah[i], bl);
                    mma_s8(D2[i][2 * jp], al[i], bh);
                    mma_s8(D1[i][2 * jp + 1], ah[i], bh + 2);
                    mma_s8(D2[i][2 * jp + 1], ah[i], bl + 2);
                    mma_s8(D2[i][2 * jp + 1], al[i], bh + 2);
                }
            }
        }
        buf = (buf == 2) ? 0 : buf + 1;
    }

    // ---- dequant + bias into smem staging ----
    CP_WAIT0();
    __syncthreads();
    float* Ct = (float*)smem;                 // [64][132]
    const int r  = lane >> 2;
    const int cc = (lane & 3) * 2;
#pragma unroll
    for (int i = 0; i < 2; ++i) {
        int row0 = wm + i * 16 + r;
        float sa0 = g_sA[bm + row0];
        float sa1 = g_sA[bm + row0 + 8];
#pragma unroll
        for (int j = 0; j < 4; ++j) {
            int col = wn + j * 8 + cc;
            float sb0 = __uint_as_float(g_sBbits[bn + col])     * (1.0f / 127.0f);
            float sb1 = __uint_as_float(g_sBbits[bn + col + 1]) * (1.0f / 127.0f);
            float b0 = bias[bn + col], b1 = bias[bn + col + 1];
            Ct[row0 * 132 + col]           = ((float)D1[i][j][0] + (float)D2[i][j][0] * (1.0f / 256.0f)) * sa0 * sb0 + b0;
            Ct[row0 * 132 + col + 1]       = ((float)D1[i][j][1] + (float)D2[i][j][1] * (1.0f / 256.0f)) * sa0 * sb1 + b1;
            Ct[(row0 + 8) * 132 + col]     = ((float)D1[i][j][2] + (float)D2[i][j][2] * (1.0f / 256.0f)) * sa1 * sb0 + b0;
            Ct[(row0 + 8) * 132 + col + 1] = ((float)D1[i][j][3] + (float)D2[i][j][3] * (1.0f / 256.0f)) * sa1 * sb1 + b1;
        }
    }
    __syncthreads();

    if (head < 20) {
        // ---- RoPE in place via table ----
#pragma unroll 4
        for (int p = 0; p < 16; ++p) {
            int idx = p * 256 + tid;
            int row = idx >> 6;
            int i   = idx & 63;
            int t   = bm + row;
            float x1 = Ct[row * 132 + i];
            float x2 = Ct[row * 132 + i + 64];
            float2 cs = g_cs[t * 64 + i];
            float y1 = x1 * cs.x - x2 * cs.y;
            float y2 = x2 * cs.x + x1 * cs.y;
            if (head < 16) { y1 *= SCALE_F; y2 *= SCALE_F; }
            Ct[row * 132 + i]      = y1;
            Ct[row * 132 + i + 64] = y2;
        }
        __syncthreads();

        // ---- fused per-row quantization ----
        {
            int row = tid >> 2;
            int l4  = tid & 3;
            int t   = bm + row;
            const float* rp = &Ct[row * 132 + l4 * 32];
            float v[32];
#pragma unroll
            for (int u = 0; u < 8; ++u)
                *(float4*)&v[u * 4] = *(const float4*)&rp[u * 4];
            float mx = 0.f;
#pragma unroll
            for (int u = 0; u < 32; ++u) mx = fmaxf(mx, fabsf(v[u]));
            mx = fmaxf(mx, __shfl_xor_sync(0xffffffffu, mx, 1));
            mx = fmaxf(mx, __shfl_xor_sync(0xffffffffu, mx, 2));
            float m = fmaxf(mx, 1e-20f);
            if (l4 == 0) {
                if (head < 16) g_sQ[(size_t)t * NH + head]         = m * (1.0f / 127.0f);
                else           g_sK[(size_t)t * NKV + (head - 16)] = m * (1.0f / 127.0f);
            }
            float inv = 127.0f / m;
            char hh[32], ll[32];
#pragma unroll
            for (int u = 0; u < 32; ++u) {
                float x = v[u] * inv;
                float hq = rintf(x);
                int l = (int)rintf((x - hq) * 256.0f);
                if (l > 127) l = 127;
                hh[u] = (char)(int)hq;
                ll[u] = (char)l;
            }
            int8_t* dh;
            int8_t* dl;
            if (head < 16) {
                size_t o = (size_t)t * (NH * HD) + head * HD + l4 * 32;
                dh = &g_Q8h[o]; dl = &g_Q8l[o];
            } else {
                size_t o = (size_t)t * (NKV * HD) + (head - 16) * HD + l4 * 32;
                dh = &g_K8h[o]; dl = &g_K8l[o];
            }
            *(uint4*)&dh[0]  = *(uint4*)&hh[0];
            *(uint4*)&dh[16] = *(uint4*)&hh[16];
            *(uint4*)&dl[0]  = *(uint4*)&ll[0];
            *(uint4*)&dl[16] = *(uint4*)&ll[16];
        }
    } else {
        // ---- V: single fp16 ----
#pragma unroll 4
        for (int p = 0; p < 16; ++p) {
            int idx = p * 256 + tid;
            int row = idx >> 6;
            int i   = idx & 63;
            int t   = bm + row;
            float x1 = Ct[row * 132 + i];
            float x2 = Ct[row * 132 + i + 64];
            size_t o = (size_t)t * (NKV * HD) + (head - 20) * HD + i;
            g_Vh[o]      = __float2half_rn(x1);
            g_Vh[o + 64] = __float2half_rn(x2);
        }
    }
}

// ---------------------------------------------------------------------------
// Stage 3: attention.  QK^T int8 2-digit, PV fp16 (single-digit V).
// 2 heads/CTA, 2-stage cp.async KV, Q staged once, occ 1.
// ---------------------------------------------------------------------------
#define K8_B 8192
#define V_B  17408
#define ASTG (2 * K8_B + V_B + 256)       // 34048
#define Q_TOTAL 32768
#define ATTN_SMEM (Q_TOTAL + 2 * ASTG)    // 100864

#define SWQ(row, chunk) ((row) * 128 + ((((chunk) ^ ((row) & 7))) << 4))

__global__ __launch_bounds__(256, 1)
void attn_mma_kernel(float* __restrict__ out) {
    extern __shared__ char smc[];
    const uint32_t smu = smem_to_u32(smc);
    const int tid  = threadIdx.x;
    const int wid  = tid >> 5;
    const int lane = tid & 31;

    const int qt   = 33 - blockIdx.x;
    const int hp   = blockIdx.y;
    const int head = hp * 2 + (wid >> 2);
    const int kvh  = hp >> 1;
    const int t0   = qt * 64;
    const int mrow = (wid & 3) * 16;

    const int r  = lane >> 2;
    const int cc = (lane & 3) * 2;

    int kts[12];
    int nkt = 0;
    if (t0 >= MMETA && qt >= 10) {
        kts[nkt++] = 0; kts[nkt++] = 1;
        for (int k = qt - 8; k <= qt; ++k) kts[nkt++] = k;
    } else {
        for (int k = 0; k <= qt; ++k) kts[nkt++] = k;
    }

    // ---- stage Q8 tiles (2 heads x 2 digits) ----
#pragma unroll
    for (int q = 0; q < 8; ++q) {
        int idx = q * 256 + tid;
        int hd  = idx >> 10;
        int rem = idx & 1023;
        int dg  = rem >> 9;
        int r2  = rem & 511;
        int row = r2 >> 3;
        int seg = r2 & 7;
        const int8_t* src = (dg ? g_Q8l : g_Q8h) +
                            (size_t)(t0 + row) * (NH * HD) + (hp * 2 + hd) * HD + seg * 16;
        cp_async16(smu + hd * 16384 + dg * 8192 + SWQ(row, seg), src);
    }

    auto issue = [&](int ti, int buf) {
        int s0 = kts[ti] * 64;
        uint32_t base = smu + Q_TOTAL + buf * ASTG;
#pragma unroll
        for (int q = 0; q < 8; ++q) {
            int idx = q * 256 + tid;
            if (idx < 1024) {
                int dg = idx >> 9, rem = idx & 511, row = rem >> 3, seg = rem & 7;
                const int8_t* src = (dg ? g_K8l : g_K8h) +
                                    (size_t)(s0 + row) * (NKV * HD) + kvh * HD + seg * 16;
                cp_async16(base + dg * K8_B + SWQ(row, seg), src);
            } else {
                int v = idx - 1024, row = v >> 4, ch = v & 15;
                const __half* src = g_Vh +
                                    (size_t)(s0 + row) * (NKV * HD) + kvh * HD + ch * 8;
                cp_async16(base + 2 * K8_B + row * 272 + ch * 16, src);
            }
        }
        if (tid < 64)
            cp_async4(base + 2 * K8_B + V_B + tid * 4, &g_sK[(size_t)(s0 + tid) * NKV + kvh]);
    };

    const int tr0 = t0 + mrow + r;
    const int tr1 = tr0 + 8;
    const float sq0 = g_sQ[(size_t)tr0 * NH + head];
    const float sq1 = g_sQ[(size_t)tr1 * NH + head];

    const int brow4 = (lane & 7) + ((lane >> 4) & 1) * 8;
    const int bc0   = (lane >> 3) & 1;
    const uint32_t voff = ((lane & 7) + ((lane >> 3) & 1) * 8) * 272 + ((lane >> 3) >> 1) * 16;

    float oacc[16][4];
#pragma unroll
    for (int j = 0; j < 16; ++j)
#pragma unroll
        for (int q = 0; q < 4; ++q) oacc[j][q] = 0.f;
    float m0 = -3.0e38f, m1 = -3.0e38f, l0 = 0.f, l1 = 0.f;

    uint32_t qh[4][4], ql[4][4];

    issue(0, 0); CP_COMMIT();

    for (int it = 0; it < nkt; ++it) {
        if (it + 1 < nkt) issue(it + 1, (it + 1) & 1);
        CP_COMMIT();
        CP_WAIT1();
        __syncthreads();

        const uint32_t base = smu + Q_TOTAL + (it & 1) * ASTG;
        const float* sKs = (const float*)(smc + Q_TOTAL + (it & 1) * ASTG + 2 * K8_B + V_B);
        const int s0 = kts[it] * 64;

        if (it == 0) {
            uint32_t qb = smu + (wid >> 2) * 16384;
#pragma unroll
            for (int kc = 0; kc < 4; ++kc) {
                uint32_t ad = qb + SWQ(mrow + (lane & 15), kc * 2 + (lane >> 4));
                ldsm_x4(qh[kc], ad);
                ldsm_x4(ql[kc], ad + 8192);
            }
        }

        // ---- S = Q K^T (int8 2-digit) ----
        int S1[8][4], S2[8][4];
#pragma unroll
        for (int j = 0; j < 8; ++j)
#pragma unroll
            for (int q = 0; q < 4; ++q) { S1[j][q] = 0; S2[j][q] = 0; }

#pragma unroll
        for (int j = 0; j < 4; ++j) {
#pragma unroll
            for (int kc = 0; kc < 4; ++kc) {
                uint32_t kh[4], kl[4];
                uint32_t bd = base + SWQ(j * 16 + brow4, kc * 2 + bc0);
                ldsm_x4(kh, bd);
                ldsm_x4(kl, bd + K8_B);
                mma_s8(S1[2 * j], qh[kc], kh);
                mma_s8(S2[2 * j], qh[kc], kl);
                mma_s8(S2[2 * j], ql[kc], kh);
                mma_s8(S1[2 * j + 1], qh[kc], kh + 2);
                mma_s8(S2[2 * j + 1], qh[kc], kl + 2);
                mma_s8(S2[2 * j + 1], ql[kc], kh + 2);
            }
        }

        // ---- dequant + mask ----
        float sacc[8][4];
#pragma unroll
        for (int j = 0; j < 8; ++j) {
            int c0 = j * 8 + cc;
            float k0s = sKs[c0], k1s = sKs[c0 + 1];
            sacc[j][0] = ((float)S1[j][0] + (float)S2[j][0] * (1.0f / 256.0f)) * (sq0 * k0s);
            sacc[j][1] = ((float)S1[j][1] + (float)S2[j][1] * (1.0f / 256.0f)) * (sq0 * k1s);
            sacc[j][2] = ((float)S1[j][2] + (float)S2[j][2] * (1.0f / 256.0f)) * (sq1 * k0s);
            sacc[j][3] = ((float)S1[j][3] + (float)S2[j][3] * (1.0f / 256.0f)) * (sq1 * k1s);
        }

#pragma unroll
        for (int j = 0; j < 8; ++j) {
            int sb0 = s0 + j * 8 + cc;
#pragma unroll
            for (int cx = 0; cx < 2; ++cx) {
                int s = sb0 + cx;
                bool v0 = (tr0 < MMETA) ? (s <= tr0)
                                        : ((s < MMETA) || ((s <= tr0) && (tr0 - s < WWIN)));
                bool v1 = (tr1 < MMETA) ? (s <= tr1)
                                        : ((s < MMETA) || ((s <= tr1) && (tr1 - s < WWIN)));
                if (!v0) sacc[j][cx]     = NEGV;
                if (!v1) sacc[j][cx + 2] = NEGV;
            }
        }

        // ---- online softmax (fp16 P, sums from rounded values) ----
        float mx0 = NEGV, mx1 = NEGV;
#pragma unroll
        for (int j = 0; j < 8; ++j) {
            mx0 = fmaxf(mx0, fmaxf(sacc[j][0], sacc[j][1]));
            mx1 = fmaxf(mx1, fmaxf(sacc[j][2], sacc[j][3]));
        }
        mx0 = fmaxf(mx0, __shfl_xor_sync(0xffffffffu, mx0, 1));
        mx0 = fmaxf(mx0, __shfl_xor_sync(0xffffffffu, mx0, 2));
        mx1 = fmaxf(mx1, __shfl_xor_sync(0xffffffffu, mx1, 1));
        mx1 = fmaxf(mx1, __shfl_xor_sync(0xffffffffu, mx1, 2));

        float mn0 = fmaxf(m0, mx0);
        float mn1 = fmaxf(m1, mx1);
        float al0 = __expf(m0 - mn0);
        float al1 = __expf(m1 - mn1);
        m0 = mn0; m1 = mn1;

        uint32_t pp[8][2];
        float sum0 = 0.f, sum1 = 0.f;
#pragma unroll
        for (int j = 0; j < 8; ++j) {
            float p0 = __expf(sacc[j][0] - m0);
            float p1 = __expf(sacc[j][1] - m0);
            float p2 = __expf(sacc[j][2] - m1);
            float p3 = __expf(sacc[j][3] - m1);
            uint32_t h0 = cvt_h2(p1, p0);
            uint32_t h1 = cvt_h2(p3, p2);
            pp[j][0] = h0;
            pp[j][1] = h1;
            float2 f0 = __half22float2(*reinterpret_cast<__half2*>(&h0));
            float2 f1 = __half22float2(*reinterpret_cast<__half2*>(&h1));
            sum0 += f0.x + f0.y;
            sum1 += f1.x + f1.y;
        }
        sum0 += __shfl_xor_sync(0xffffffffu, sum0, 1);
        sum0 += __shfl_xor_sync(0xffffffffu, sum0, 2);
        sum1 += __shfl_xor_sync(0xffffffffu, sum1, 1);
        sum1 += __shfl_xor_sync(0xffffffffu, sum1, 2);
        l0 = l0 * al0 + sum0;
        l1 = l1 * al1 + sum1;

#pragma unroll
        for (int j = 0; j < 16; ++j) {
            oacc[j][0] *= al0; oacc[j][1] *= al0;
            oacc[j][2] *= al1; oacc[j][3] *= al1;
        }

        // ---- O += P V (fp16, single-digit V) ----
        const uint32_t vbase = base + 2 * K8_B;
#pragma unroll
        for (int kt = 0; kt < 4; ++kt) {
            uint32_t phi[4] = { pp[2 * kt][0], pp[2 * kt][1], pp[2 * kt + 1][0], pp[2 * kt + 1][1] };
            uint32_t ktb = vbase + kt * (16 * 272) + voff;
#pragma unroll
            for (int j2 = 0; j2 < 8; ++j2) {
                uint32_t vh[4];
                ldsm_x4t(vh, ktb + j2 * 32);
                mma_f16(oacc[2 * j2], phi, vh);
                mma_f16(oacc[2 * j2 + 1], phi, vh + 2);
            }
        }
        __syncthreads();
    }

    float inv0 = 1.0f / l0;
    float inv1 = 1.0f / l1;
    float* ob0 = &out[(size_t)tr0 * (NH * HD) + head * HD + cc];
    float* ob1 = &out[(size_t)tr1 * (NH * HD) + head * HD + cc];
#pragma unroll
    for (int j = 0; j < 16; ++j) {
        float2 v0 = { oacc[j][0] * inv0, oacc[j][1] * inv0 };
        float2 v1 = { oacc[j][2] * inv1, oacc[j][3] * inv1 };
        *(float2*)&ob0[j * 8] = v0;
        *(float2*)&ob1[j * 8] = v1;
    }
}

// ---------------------------------------------------------------------------
extern "C" void kernel_launch(void* const* d_in, const int* in_sizes, int n_in,
                              void* d_out, int out_size) {
    const float* hs   = (const float*)d_in[0];
    const float* w    = (const float*)d_in[1];
    const float* bias = (const float*)d_in[2];
    const int*   pos  = (const int*)d_in[3];
    float* out = (float*)d_out;

    init_invfreq_kernel<<<1, 64>>>();
    cs_table_kernel<<<(T_TOK * 64 + 255) / 256, 256>>>(pos);
    quant_a_kernel<<<T_TOK, 256>>>(hs);
    w_colmax_kernel<<<dim3(NQKV / 4 / 256, HS / 32), 256>>>(w);
    quant_w_kernel<<<dim3(NQKV / 64, HS / 64), 256>>>(w);

    cudaFuncSetAttribute(qkv_mma_kernel, cudaFuncAttributeMaxDynamicSharedMemorySize, GEMM_SMEM);
    qkv_mma_kernel<<<dim3(24, T_TOK / 64), 256, GEMM_SMEM>>>(bias);

    cudaFuncSetAttribute(attn_mma_kernel, cudaFuncAttributeMaxDynamicSharedMemorySize, ATTN_SMEM);
    attn_mma_kernel<<<dim3(34, 8), 256, ATTN_SMEM>>>(out);
}